// round 3
// baseline (speedup 1.0000x reference)
#include <cuda_runtime.h>
#include <cuda_bf16.h>
#include <mma.h>
#include <math.h>

using namespace nvcuda;

#define B_  2
#define T_  2048
#define C_  1024
#define H_  16
#define D_  64
#define M_  (B_ * T_)   // 4096 rows

// ---------------- scratch (device globals: no allocation allowed) ----------
__device__ __align__(128) float g_q[(size_t)M_ * C_];
__device__ __align__(128) float g_k[(size_t)M_ * C_];
__device__ __align__(128) float g_v[(size_t)M_ * C_];
__device__ __align__(128) float g_o[(size_t)M_ * C_];
__device__ __align__(128) float2 g_rope_tab[T_ * 32];

// ---------------- cp.async helpers -----------------------------------------
__device__ __forceinline__ void cp16(void* smem_dst, const void* gmem_src) {
    unsigned s = (unsigned)__cvta_generic_to_shared(smem_dst);
    asm volatile("cp.async.cg.shared.global [%0], [%1], 16;\n"
                 :: "r"(s), "l"(gmem_src));
}
#define CP_COMMIT()  asm volatile("cp.async.commit_group;\n")
#define CP_WAIT(n)   asm volatile("cp.async.wait_group %0;\n" :: "n"(n))

// ---------------------------------------------------------------------------
// GEMM: Y[M,N] = A[M,K] @ B[N,K]^T, tf32 wmma.
// 128x128 block tile, BK=32, 256 threads (8 warps, each 32x64),
// cp.async double-buffered shared pipeline.
// ---------------------------------------------------------------------------
#define GST 36

__global__ __launch_bounds__(256) void gemm_tn(
    const float* __restrict__ A, const float* __restrict__ Bm,
    float* __restrict__ Y, int M, int N, int K)
{
    extern __shared__ float sg[];
    float* As = sg;                    // 2 x 128 x GST
    float* Bs = sg + 2 * 128 * GST;    // 2 x 128 x GST

    const int m0  = blockIdx.y * 128;
    const int n0  = blockIdx.x * 128;
    const int tid = threadIdx.x;
    const int w   = tid >> 5;
    const int wm  = w >> 1;    // 0..3 -> 32-row strip
    const int wn  = w & 1;     // 0..1 -> 64-col strip

    wmma::fragment<wmma::accumulator, 16, 16, 8, float> acc[2][4];
#pragma unroll
    for (int i = 0; i < 2; i++)
#pragma unroll
        for (int j = 0; j < 4; j++) wmma::fill_fragment(acc[i][j], 0.0f);

    auto load_stage = [&](int buf, int kc) {
#pragma unroll
        for (int i = tid; i < 1024; i += 256) {
            int r = i >> 3;
            int c = (i & 7) << 2;
            cp16(&As[buf * 128 * GST + r * GST + c],
                 &A[(size_t)(m0 + r) * K + kc + c]);
            cp16(&Bs[buf * 128 * GST + r * GST + c],
                 &Bm[(size_t)(n0 + r) * K + kc + c]);
        }
    };

    load_stage(0, 0);
    CP_COMMIT();

    const int NIT = K / 32;
    for (int it = 0; it < NIT; it++) {
        if (it + 1 < NIT) {
            load_stage((it + 1) & 1, (it + 1) * 32);
            CP_COMMIT();
            CP_WAIT(1);
        } else {
            CP_WAIT(0);
        }
        __syncthreads();

        const float* Ab = &As[(it & 1) * 128 * GST];
        const float* Bb = &Bs[(it & 1) * 128 * GST];

#pragma unroll
        for (int k8 = 0; k8 < 4; k8++) {
            wmma::fragment<wmma::matrix_a, 16, 16, 8, wmma::precision::tf32,
                           wmma::row_major> a[2];
            wmma::fragment<wmma::matrix_b, 16, 16, 8, wmma::precision::tf32,
                           wmma::col_major> b[4];
#pragma unroll
            for (int i = 0; i < 2; i++) {
                wmma::load_matrix_sync(a[i],
                    &Ab[(wm * 32 + i * 16) * GST + k8 * 8], GST);
#pragma unroll
                for (int e = 0; e < a[i].num_elements; e++)
                    a[i].x[e] = wmma::__float_to_tf32(a[i].x[e]);
            }
#pragma unroll
            for (int j = 0; j < 4; j++) {
                wmma::load_matrix_sync(b[j],
                    &Bb[(wn * 64 + j * 16) * GST + k8 * 8], GST);
#pragma unroll
                for (int e = 0; e < b[j].num_elements; e++)
                    b[j].x[e] = wmma::__float_to_tf32(b[j].x[e]);
            }
#pragma unroll
            for (int i = 0; i < 2; i++)
#pragma unroll
                for (int j = 0; j < 4; j++)
                    wmma::mma_sync(acc[i][j], a[i], b[j], acc[i][j]);
        }
        __syncthreads();
    }

#pragma unroll
    for (int i = 0; i < 2; i++)
#pragma unroll
        for (int j = 0; j < 4; j++)
            wmma::store_matrix_sync(
                &Y[(size_t)(m0 + wm * 32 + i * 16) * N + n0 + wn * 64 + j * 16],
                acc[i][j], N, wmma::mem_row_major);
}

// ---------------------------------------------------------------------------
// RoPE table + apply
// ---------------------------------------------------------------------------
__global__ __launch_bounds__(256) void rope_table_kernel(float2* __restrict__ tab)
{
    int idx = blockIdx.x * blockDim.x + threadIdx.x;
    if (idx >= T_ * 32) return;
    int t = idx >> 5;
    int j = idx & 31;
    double inv = exp(-((double)(2 * j) / 64.0) * log(10000.0));
    double ang = (double)t * inv;
    tab[idx] = make_float2((float)cos(ang), (float)sin(ang));
}

__global__ __launch_bounds__(256) void rope_apply_kernel(
    float* __restrict__ q, float* __restrict__ k,
    const float2* __restrict__ tab)
{
    int idx = blockIdx.x * blockDim.x + threadIdx.x;
    const int total = M_ * (C_ / 2);
    if (idx >= total) return;

    int row  = idx >> 9;
    int col2 = idx & 511;
    int t    = row & (T_ - 1);
    int j    = col2 & 31;
    int head = col2 >> 5;

    float2 cs = tab[t * 32 + j];
    size_t base = (size_t)row * C_ + head * D_ + 2 * j;

    float2 qv = *(float2*)&q[base];
    float2 kv = *(float2*)&k[base];
    *(float2*)&q[base] = make_float2(qv.x * cs.x - qv.y * cs.y,
                                     qv.x * cs.y + qv.y * cs.x);
    *(float2*)&k[base] = make_float2(kv.x * cs.x - kv.y * cs.y,
                                     kv.x * cs.y + kv.y * cs.x);
}

// ---------------------------------------------------------------------------
// Flash attention (causal). BM=128, BN=64, D=64, 8 warps (256 thr).
// cp.async double-buffered K/V; PV result written back into Ss strip
// (warp-local) so no extra Pt buffer; scale folded into Q load.
// ---------------------------------------------------------------------------
#define FST 72

__global__ __launch_bounds__(256) void flash_kernel(
    const float* __restrict__ q, const float* __restrict__ k,
    const float* __restrict__ v, float* __restrict__ o)
{
    extern __shared__ float sm[];
    float* Qs    = sm;                    // 128*FST
    float* Kbase = sm + 128 * FST;        // 2 x 64*FST
    float* Vbase = sm + 256 * FST;        // 2 x 64*FST
    float* Ss    = sm + 384 * FST;        // 128*FST (scores -> probs -> PV)
    float* Os    = sm + 512 * FST;        // 128*FST

    __shared__ float m_sh[128], l_sh[128], a_sh[128];

    const int bh  = blockIdx.y;
    const int b   = bh >> 4;
    const int h   = bh & 15;
    const int q0  = (gridDim.x - 1 - blockIdx.x) * 128;   // heavy blocks first
    const int tid = threadIdx.x;
    const int w   = tid >> 5;
    const float scale = 0.125f;

    const size_t qrow = (size_t)(b * T_ + q0) * C_ + h * D_;

    // load Q tile (scaled)
    for (int i = tid; i < 2048; i += 256) {
        int r = i >> 4, c = (i & 15) << 2;
        float4 t4 = *(const float4*)&q[qrow + (size_t)r * C_ + c];
        t4.x *= scale; t4.y *= scale; t4.z *= scale; t4.w *= scale;
        *(float4*)&Qs[r * FST + c] = t4;
    }
    for (int i = tid; i < 8192; i += 256) {
        int r = i >> 6, c = i & 63;
        Os[r * FST + c] = 0.0f;
    }
    if (tid < 128) { m_sh[tid] = -INFINITY; l_sh[tid] = 0.0f; }

    auto kv_load = [&](int buf, int n0) {
        const size_t krow = (size_t)(b * T_ + n0) * C_ + h * D_;
#pragma unroll
        for (int i = tid; i < 1024; i += 256) {
            int r = i >> 4, c = (i & 15) << 2;
            cp16(&Kbase[buf * 64 * FST + r * FST + c],
                 &k[krow + (size_t)r * C_ + c]);
            cp16(&Vbase[buf * 64 * FST + r * FST + c],
                 &v[krow + (size_t)r * C_ + c]);
        }
    };

    kv_load(0, 0);
    CP_COMMIT();

    const int nend = q0 + 64;   // last KV tile start
    for (int n0 = 0; n0 <= nend; n0 += 64) {
        const int buf = (n0 >> 6) & 1;
        if (n0 + 64 <= nend) {
            kv_load(buf ^ 1, n0 + 64);
            CP_COMMIT();
            CP_WAIT(1);
        } else {
            CP_WAIT(0);
        }
        __syncthreads();

        const float* Ks = &Kbase[buf * 64 * FST];
        const float* Vs = &Vbase[buf * 64 * FST];

        // ---- S = Q K^T (warp: 16-row strip x 64 cols) ----
        {
            wmma::fragment<wmma::accumulator, 16, 16, 8, float> sacc[4];
#pragma unroll
            for (int i = 0; i < 4; i++) wmma::fill_fragment(sacc[i], 0.0f);
#pragma unroll
            for (int k8 = 0; k8 < 8; k8++) {
                wmma::fragment<wmma::matrix_a, 16, 16, 8,
                               wmma::precision::tf32, wmma::row_major> a;
                wmma::load_matrix_sync(a, &Qs[w * 16 * FST + k8 * 8], FST);
#pragma unroll
                for (int i = 0; i < a.num_elements; i++)
                    a.x[i] = wmma::__float_to_tf32(a.x[i]);
#pragma unroll
                for (int nt = 0; nt < 4; nt++) {
                    wmma::fragment<wmma::matrix_b, 16, 16, 8,
                                   wmma::precision::tf32, wmma::col_major> bb;
                    wmma::load_matrix_sync(bb, &Ks[nt * 16 * FST + k8 * 8], FST);
#pragma unroll
                    for (int i = 0; i < bb.num_elements; i++)
                        bb.x[i] = wmma::__float_to_tf32(bb.x[i]);
                    wmma::mma_sync(sacc[nt], a, bb, sacc[nt]);
                }
            }
#pragma unroll
            for (int nt = 0; nt < 4; nt++)
                wmma::store_matrix_sync(&Ss[w * 16 * FST + nt * 16], sacc[nt],
                                        FST, wmma::mem_row_major);
        }
        __syncthreads();

        // ---- online softmax: 2 threads per row ----
        {
            const int r    = tid >> 1;
            const int half = tid & 1;
            const int cbase = half * 32;
            const int cmaxl = q0 + r - n0;    // allowed local col (may be <0 or >63)

            float mo = m_sh[r];
            float mx = -INFINITY;
            const int chi = min(31, cmaxl - cbase);
            for (int c = 0; c <= chi; c++)
                mx = fmaxf(mx, Ss[r * FST + cbase + c]);
            mx = fmaxf(mx, __shfl_xor_sync(0xffffffffu, mx, 1));
            float newm = fmaxf(mo, mx);
            float alpha = __expf(mo - newm);
            float sum = 0.0f;
#pragma unroll
            for (int c = 0; c < 32; c++) {
                int cc = cbase + c;
                float p = (cc <= cmaxl) ? __expf(Ss[r * FST + cc] - newm) : 0.0f;
                Ss[r * FST + cc] = p;
                sum += p;
            }
            sum += __shfl_xor_sync(0xffffffffu, sum, 1);
            if (half == 0) {
                m_sh[r] = newm;
                l_sh[r] = l_sh[r] * alpha + sum;
                a_sh[r] = alpha;
            }
        }
        __syncthreads();

        // ---- PV: result overwrites this warp's own Ss strip ----
        {
            wmma::fragment<wmma::accumulator, 16, 16, 8, float> oacc[4];
#pragma unroll
            for (int i = 0; i < 4; i++) wmma::fill_fragment(oacc[i], 0.0f);
#pragma unroll
            for (int k8 = 0; k8 < 8; k8++) {
                wmma::fragment<wmma::matrix_a, 16, 16, 8,
                               wmma::precision::tf32, wmma::row_major> a;
                wmma::load_matrix_sync(a, &Ss[w * 16 * FST + k8 * 8], FST);
#pragma unroll
                for (int i = 0; i < a.num_elements; i++)
                    a.x[i] = wmma::__float_to_tf32(a.x[i]);
#pragma unroll
                for (int dt = 0; dt < 4; dt++) {
                    wmma::fragment<wmma::matrix_b, 16, 16, 8,
                                   wmma::precision::tf32, wmma::row_major> bb;
                    wmma::load_matrix_sync(bb, &Vs[k8 * 8 * FST + dt * 16], FST);
#pragma unroll
                    for (int i = 0; i < bb.num_elements; i++)
                        bb.x[i] = wmma::__float_to_tf32(bb.x[i]);
                    wmma::mma_sync(oacc[dt], a, bb, oacc[dt]);
                }
            }
#pragma unroll
            for (int dt = 0; dt < 4; dt++)
                wmma::store_matrix_sync(&Ss[w * 16 * FST + dt * 16], oacc[dt],
                                        FST, wmma::mem_row_major);
        }
        __syncthreads();

        // ---- merge: O = O*alpha + PV ----
        for (int i = tid; i < 8192; i += 256) {
            int r = i >> 6, c = i & 63;
            Os[r * FST + c] = Os[r * FST + c] * a_sh[r] + Ss[r * FST + c];
        }
        __syncthreads();
    }

    // ---- normalize + write ----
    for (int i = tid; i < 8192; i += 256) {
        int r = i >> 6, c = i & 63;
        o[qrow + (size_t)r * C_ + c] = Os[r * FST + c] / l_sh[r];
    }
}

// ---------------------------------------------------------------------------
extern "C" void kernel_launch(void* const* d_in, const int* in_sizes, int n_in,
                              void* d_out, int out_size)
{
    (void)in_sizes; (void)n_in; (void)out_size;
    const float* x  = (const float*)d_in[0];
    const float* Wq = (const float*)d_in[1];
    const float* Wk = (const float*)d_in[2];
    const float* Wv = (const float*)d_in[3];
    const float* Wo = (const float*)d_in[4];
    float* out = (float*)d_out;

    float *q, *k, *v, *ob;
    float2* tab;
    cudaGetSymbolAddress((void**)&q,   g_q);
    cudaGetSymbolAddress((void**)&k,   g_k);
    cudaGetSymbolAddress((void**)&v,   g_v);
    cudaGetSymbolAddress((void**)&ob,  g_o);
    cudaGetSymbolAddress((void**)&tab, g_rope_tab);

    const int gsmem = 4 * 128 * GST * (int)sizeof(float);   // 73,728 B
    cudaFuncSetAttribute(gemm_tn,
                         cudaFuncAttributeMaxDynamicSharedMemorySize, gsmem);
    const dim3 gg(C_ / 128, M_ / 128);   // (8, 32)

    rope_table_kernel<<<(T_ * 32 + 255) / 256, 256>>>(tab);

    gemm_tn<<<gg, 256, gsmem>>>(x, Wq, q, M_, C_, C_);
    gemm_tn<<<gg, 256, gsmem>>>(x, Wk, k, M_, C_, C_);
    gemm_tn<<<gg, 256, gsmem>>>(x, Wv, v, M_, C_, C_);

    const int pairs = M_ * (C_ / 2);
    rope_apply_kernel<<<(pairs + 255) / 256, 256>>>(q, k, tab);

    const int fsmem = 640 * FST * (int)sizeof(float);       // 184,320 B
    cudaFuncSetAttribute(flash_kernel,
                         cudaFuncAttributeMaxDynamicSharedMemorySize, fsmem);
    flash_kernel<<<dim3(T_ / 128, B_ * H_), 256, fsmem>>>(q, k, v, ob);

    gemm_tn<<<gg, 256, gsmem>>>(ob, Wo, out, M_, C_, C_);
}

// round 4
// speedup vs baseline: 1.6279x; 1.6279x over previous
#include <cuda_runtime.h>
#include <cuda_bf16.h>
#include <mma.h>
#include <math.h>

using namespace nvcuda;

#define B_  2
#define T_  2048
#define C_  1024
#define H_  16
#define D_  64
#define M_  (B_ * T_)   // 4096 rows

// ---------------- scratch (device globals: no allocation allowed) ----------
__device__ __align__(128) float g_q[(size_t)M_ * C_];
__device__ __align__(128) float g_k[(size_t)M_ * C_];
__device__ __align__(128) float g_v[(size_t)M_ * C_];
__device__ __align__(128) float g_o[(size_t)M_ * C_];
__device__ __align__(128) float2 g_rope_tab[T_ * 32];

// ---------------- cp.async helpers -----------------------------------------
__device__ __forceinline__ void cp16(void* smem_dst, const void* gmem_src) {
    unsigned s = (unsigned)__cvta_generic_to_shared(smem_dst);
    asm volatile("cp.async.cg.shared.global [%0], [%1], 16;\n"
                 :: "r"(s), "l"(gmem_src));
}
#define CP_COMMIT()  asm volatile("cp.async.commit_group;\n")
#define CP_WAIT(n)   asm volatile("cp.async.wait_group %0;\n" :: "n"(n))

// ---------------- mma.sync m16n8k8 tf32 helpers -----------------------------
__device__ __forceinline__ unsigned f2tf(float f) {
    unsigned u;
    asm("cvt.rna.tf32.f32 %0, %1;" : "=r"(u) : "f"(f));
    return u;
}
__device__ __forceinline__ void mma8(float* d, const unsigned* a,
                                     const unsigned* b) {
    asm volatile(
        "mma.sync.aligned.m16n8k8.row.col.f32.tf32.tf32.f32 "
        "{%0,%1,%2,%3}, {%4,%5,%6,%7}, {%8,%9}, {%0,%1,%2,%3};"
        : "+f"(d[0]), "+f"(d[1]), "+f"(d[2]), "+f"(d[3])
        : "r"(a[0]), "r"(a[1]), "r"(a[2]), "r"(a[3]),
          "r"(b[0]), "r"(b[1]));
}

// ---------------------------------------------------------------------------
// GEMM: Y[M,N] = A[M,K] @ B[N,K]^T, tf32 wmma, 128x128 tile, cp.async x2.
// ---------------------------------------------------------------------------
#define GST 36

__global__ __launch_bounds__(256) void gemm_tn(
    const float* __restrict__ A, const float* __restrict__ Bm,
    float* __restrict__ Y, int M, int N, int K)
{
    extern __shared__ float sg[];
    float* As = sg;
    float* Bs = sg + 2 * 128 * GST;

    const int m0  = blockIdx.y * 128;
    const int n0  = blockIdx.x * 128;
    const int tid = threadIdx.x;
    const int w   = tid >> 5;
    const int wm  = w >> 1;
    const int wn  = w & 1;

    wmma::fragment<wmma::accumulator, 16, 16, 8, float> acc[2][4];
#pragma unroll
    for (int i = 0; i < 2; i++)
#pragma unroll
        for (int j = 0; j < 4; j++) wmma::fill_fragment(acc[i][j], 0.0f);

    auto load_stage = [&](int buf, int kc) {
#pragma unroll
        for (int i = tid; i < 1024; i += 256) {
            int r = i >> 3;
            int c = (i & 7) << 2;
            cp16(&As[buf * 128 * GST + r * GST + c],
                 &A[(size_t)(m0 + r) * K + kc + c]);
            cp16(&Bs[buf * 128 * GST + r * GST + c],
                 &Bm[(size_t)(n0 + r) * K + kc + c]);
        }
    };

    load_stage(0, 0);
    CP_COMMIT();

    const int NIT = K / 32;
    for (int it = 0; it < NIT; it++) {
        if (it + 1 < NIT) {
            load_stage((it + 1) & 1, (it + 1) * 32);
            CP_COMMIT();
            CP_WAIT(1);
        } else {
            CP_WAIT(0);
        }
        __syncthreads();

        const float* Ab = &As[(it & 1) * 128 * GST];
        const float* Bb = &Bs[(it & 1) * 128 * GST];

#pragma unroll
        for (int k8 = 0; k8 < 4; k8++) {
            wmma::fragment<wmma::matrix_a, 16, 16, 8, wmma::precision::tf32,
                           wmma::row_major> a[2];
            wmma::fragment<wmma::matrix_b, 16, 16, 8, wmma::precision::tf32,
                           wmma::col_major> b[4];
#pragma unroll
            for (int i = 0; i < 2; i++) {
                wmma::load_matrix_sync(a[i],
                    &Ab[(wm * 32 + i * 16) * GST + k8 * 8], GST);
#pragma unroll
                for (int e = 0; e < a[i].num_elements; e++)
                    a[i].x[e] = wmma::__float_to_tf32(a[i].x[e]);
            }
#pragma unroll
            for (int j = 0; j < 4; j++) {
                wmma::load_matrix_sync(b[j],
                    &Bb[(wn * 64 + j * 16) * GST + k8 * 8], GST);
#pragma unroll
                for (int e = 0; e < b[j].num_elements; e++)
                    b[j].x[e] = wmma::__float_to_tf32(b[j].x[e]);
            }
#pragma unroll
            for (int i = 0; i < 2; i++)
#pragma unroll
                for (int j = 0; j < 4; j++)
                    wmma::mma_sync(acc[i][j], a[i], b[j], acc[i][j]);
        }
        __syncthreads();
    }

#pragma unroll
    for (int i = 0; i < 2; i++)
#pragma unroll
        for (int j = 0; j < 4; j++)
            wmma::store_matrix_sync(
                &Y[(size_t)(m0 + wm * 32 + i * 16) * N + n0 + wn * 64 + j * 16],
                acc[i][j], N, wmma::mem_row_major);
}

// ---------------------------------------------------------------------------
// RoPE table + apply
// ---------------------------------------------------------------------------
__global__ __launch_bounds__(256) void rope_table_kernel(float2* __restrict__ tab)
{
    int idx = blockIdx.x * blockDim.x + threadIdx.x;
    if (idx >= T_ * 32) return;
    int t = idx >> 5;
    int j = idx & 31;
    double inv = exp(-((double)(2 * j) / 64.0) * log(10000.0));
    double ang = (double)t * inv;
    tab[idx] = make_float2((float)cos(ang), (float)sin(ang));
}

__global__ __launch_bounds__(256) void rope_apply_kernel(
    float* __restrict__ q, float* __restrict__ k,
    const float2* __restrict__ tab)
{
    int idx = blockIdx.x * blockDim.x + threadIdx.x;
    const int total = M_ * (C_ / 2);
    if (idx >= total) return;

    int row  = idx >> 9;
    int col2 = idx & 511;
    int t    = row & (T_ - 1);
    int j    = col2 & 31;
    int head = col2 >> 5;

    float2 cs = tab[t * 32 + j];
    size_t base = (size_t)row * C_ + head * D_ + 2 * j;

    float2 qv = *(float2*)&q[base];
    float2 kv = *(float2*)&k[base];
    *(float2*)&q[base] = make_float2(qv.x * cs.x - qv.y * cs.y,
                                     qv.x * cs.y + qv.y * cs.x);
    *(float2*)&k[base] = make_float2(kv.x * cs.x - kv.y * cs.y,
                                     kv.x * cs.y + kv.y * cs.x);
}

// ---------------------------------------------------------------------------
// Flash attention (causal), FlashAttention-2 style:
// BM=64 (4 warps x 16 rows), BN=64, D=64.
// mma.sync m16n8k8 tf32; Q and O register-resident; softmax in registers
// with quad shuffles; P via warp-private smem strip (reuses Q staging).
// K/V double-buffered via cp.async.
// ---------------------------------------------------------------------------
#define FST 68

__global__ __launch_bounds__(128, 2) void flash_kernel(
    const float* __restrict__ q, const float* __restrict__ k,
    const float* __restrict__ v, float* __restrict__ o)
{
    extern __shared__ float sm[];
    float* QP = sm;                   // 64*FST: Q staging, then P strips
    float* Kb = sm + 64 * FST;        // 2 x 64*FST
    float* Vb = sm + 192 * FST;       // 2 x 64*FST

    const int bh  = blockIdx.y;
    const int b   = bh >> 4;
    const int h   = bh & 15;
    const int q0  = (gridDim.x - 1 - blockIdx.x) * 64;  // heavy blocks first
    const int tid = threadIdx.x;
    const int w   = tid >> 5;
    const int l   = tid & 31;
    const int g   = l >> 2;   // row group 0..7
    const int qd  = l & 3;    // quad lane 0..3
    const float scale = 0.125f;

    const size_t qrow = (size_t)(b * T_ + q0) * C_ + h * D_;

    auto kv_load = [&](int buf, int n0) {
        const size_t krow = (size_t)(b * T_ + n0) * C_ + h * D_;
#pragma unroll
        for (int i = tid; i < 1024; i += 128) {
            int r = i >> 4, c = (i & 15) << 2;
            cp16(&Kb[buf * 64 * FST + r * FST + c],
                 &k[krow + (size_t)r * C_ + c]);
            cp16(&Vb[buf * 64 * FST + r * FST + c],
                 &v[krow + (size_t)r * C_ + c]);
        }
    };

    kv_load(0, 0);
    CP_COMMIT();

    // stage Q (scaled) into smem
    for (int i = tid; i < 1024; i += 128) {
        int r = i >> 4, c = (i & 15) << 2;
        float4 t4 = *(const float4*)&q[qrow + (size_t)r * C_ + c];
        t4.x *= scale; t4.y *= scale; t4.z *= scale; t4.w *= scale;
        *(float4*)&QP[r * FST + c] = t4;
    }
    __syncthreads();

    // Q fragments (warp-private rows w*16..w*16+15), persistent in regs
    unsigned aq[8][4];
    float* Pw = QP + w * 16 * FST;     // warp strip: Q now, P later
    {
#pragma unroll
        for (int kt = 0; kt < 8; kt++) {
            aq[kt][0] = f2tf(Pw[g * FST + kt * 8 + qd]);
            aq[kt][1] = f2tf(Pw[(g + 8) * FST + kt * 8 + qd]);
            aq[kt][2] = f2tf(Pw[g * FST + kt * 8 + qd + 4]);
            aq[kt][3] = f2tf(Pw[(g + 8) * FST + kt * 8 + qd + 4]);
        }
    }
    __syncwarp();

    float oacc[8][4];
#pragma unroll
    for (int nt = 0; nt < 8; nt++)
#pragma unroll
        for (int j = 0; j < 4; j++) oacc[nt][j] = 0.0f;
    float mA = -INFINITY, mB = -INFINITY, lA = 0.0f, lB = 0.0f;

    const int rA_loc = w * 16 + g;      // local row of c0/c1
    const int rB_loc = rA_loc + 8;      // local row of c2/c3

    for (int n0 = 0; n0 <= q0; n0 += 64) {
        const int buf = (n0 >> 6) & 1;
        if (n0 + 64 <= q0) {
            kv_load(buf ^ 1, n0 + 64);
            CP_COMMIT();
            CP_WAIT(1);
        } else {
            CP_WAIT(0);
        }
        __syncthreads();

        const float* Ks = &Kb[buf * 64 * FST];
        const float* Vs = &Vb[buf * 64 * FST];

        // ---- S = Q K^T : s[nt] is 16x8 tile ----
        float s[8][4];
#pragma unroll
        for (int nt = 0; nt < 8; nt++)
#pragma unroll
            for (int j = 0; j < 4; j++) s[nt][j] = 0.0f;

#pragma unroll
        for (int kt = 0; kt < 8; kt++) {
#pragma unroll
            for (int nt = 0; nt < 8; nt++) {
                unsigned bb[2];
                bb[0] = f2tf(Ks[(nt * 8 + g) * FST + kt * 8 + qd]);
                bb[1] = f2tf(Ks[(nt * 8 + g) * FST + kt * 8 + qd + 4]);
                mma8(s[nt], aq[kt], bb);
            }
        }

        // ---- causal mask (diagonal tile only) ----
        if (n0 == q0) {
#pragma unroll
            for (int nt = 0; nt < 8; nt++) {
                int c0 = nt * 8 + 2 * qd;
                if (c0     > rA_loc) s[nt][0] = -INFINITY;
                if (c0 + 1 > rA_loc) s[nt][1] = -INFINITY;
                if (c0     > rB_loc) s[nt][2] = -INFINITY;
                if (c0 + 1 > rB_loc) s[nt][3] = -INFINITY;
            }
        }

        // ---- register softmax (row halves A and B) ----
        float mxA = -INFINITY, mxB = -INFINITY;
#pragma unroll
        for (int nt = 0; nt < 8; nt++) {
            mxA = fmaxf(mxA, fmaxf(s[nt][0], s[nt][1]));
            mxB = fmaxf(mxB, fmaxf(s[nt][2], s[nt][3]));
        }
        mxA = fmaxf(mxA, __shfl_xor_sync(0xffffffffu, mxA, 1));
        mxA = fmaxf(mxA, __shfl_xor_sync(0xffffffffu, mxA, 2));
        mxB = fmaxf(mxB, __shfl_xor_sync(0xffffffffu, mxB, 1));
        mxB = fmaxf(mxB, __shfl_xor_sync(0xffffffffu, mxB, 2));

        float nmA = fmaxf(mA, mxA);
        float nmB = fmaxf(mB, mxB);
        float alA = __expf(mA - nmA);
        float alB = __expf(mB - nmB);
        mA = nmA; mB = nmB;

        float sumA = 0.0f, sumB = 0.0f;
#pragma unroll
        for (int nt = 0; nt < 8; nt++) {
            float p0 = __expf(s[nt][0] - nmA);
            float p1 = __expf(s[nt][1] - nmA);
            float p2 = __expf(s[nt][2] - nmB);
            float p3 = __expf(s[nt][3] - nmB);
            s[nt][0] = p0; s[nt][1] = p1; s[nt][2] = p2; s[nt][3] = p3;
            sumA += p0 + p1;
            sumB += p2 + p3;
        }
        sumA += __shfl_xor_sync(0xffffffffu, sumA, 1);
        sumA += __shfl_xor_sync(0xffffffffu, sumA, 2);
        sumB += __shfl_xor_sync(0xffffffffu, sumB, 1);
        sumB += __shfl_xor_sync(0xffffffffu, sumB, 2);
        lA = lA * alA + sumA;
        lB = lB * alB + sumB;

        // scale existing O
#pragma unroll
        for (int nt = 0; nt < 8; nt++) {
            oacc[nt][0] *= alA; oacc[nt][1] *= alA;
            oacc[nt][2] *= alB; oacc[nt][3] *= alB;
        }

        // ---- P to warp-private strip, reload as A fragments ----
#pragma unroll
        for (int nt = 0; nt < 8; nt++) {
            *(float2*)&Pw[g * FST + nt * 8 + 2 * qd] =
                make_float2(s[nt][0], s[nt][1]);
            *(float2*)&Pw[(g + 8) * FST + nt * 8 + 2 * qd] =
                make_float2(s[nt][2], s[nt][3]);
        }
        __syncwarp();

        // ---- O += P V ----
#pragma unroll
        for (int kt = 0; kt < 8; kt++) {
            unsigned ap[4];
            ap[0] = f2tf(Pw[g * FST + kt * 8 + qd]);
            ap[1] = f2tf(Pw[(g + 8) * FST + kt * 8 + qd]);
            ap[2] = f2tf(Pw[g * FST + kt * 8 + qd + 4]);
            ap[3] = f2tf(Pw[(g + 8) * FST + kt * 8 + qd + 4]);
#pragma unroll
            for (int nt = 0; nt < 8; nt++) {
                unsigned bb[2];
                bb[0] = f2tf(Vs[(kt * 8 + qd) * FST + nt * 8 + g]);
                bb[1] = f2tf(Vs[(kt * 8 + qd + 4) * FST + nt * 8 + g]);
                mma8(oacc[nt], ap, bb);
            }
        }
        __syncthreads();   // protect K/V buffers before next prefetch reuse
    }

    // ---- normalize + write ----
    const float rA = 1.0f / lA;
    const float rB = 1.0f / lB;
#pragma unroll
    for (int nt = 0; nt < 8; nt++) {
        int c0 = nt * 8 + 2 * qd;
        *(float2*)&o[qrow + (size_t)rA_loc * C_ + c0] =
            make_float2(oacc[nt][0] * rA, oacc[nt][1] * rA);
        *(float2*)&o[qrow + (size_t)rB_loc * C_ + c0] =
            make_float2(oacc[nt][2] * rB, oacc[nt][3] * rB);
    }
}

// ---------------------------------------------------------------------------
extern "C" void kernel_launch(void* const* d_in, const int* in_sizes, int n_in,
                              void* d_out, int out_size)
{
    (void)in_sizes; (void)n_in; (void)out_size;
    const float* x  = (const float*)d_in[0];
    const float* Wq = (const float*)d_in[1];
    const float* Wk = (const float*)d_in[2];
    const float* Wv = (const float*)d_in[3];
    const float* Wo = (const float*)d_in[4];
    float* out = (float*)d_out;

    float *q, *k, *v, *ob;
    float2* tab;
    cudaGetSymbolAddress((void**)&q,   g_q);
    cudaGetSymbolAddress((void**)&k,   g_k);
    cudaGetSymbolAddress((void**)&v,   g_v);
    cudaGetSymbolAddress((void**)&ob,  g_o);
    cudaGetSymbolAddress((void**)&tab, g_rope_tab);

    const int gsmem = 4 * 128 * GST * (int)sizeof(float);
    cudaFuncSetAttribute(gemm_tn,
                         cudaFuncAttributeMaxDynamicSharedMemorySize, gsmem);
    const dim3 gg(C_ / 128, M_ / 128);

    rope_table_kernel<<<(T_ * 32 + 255) / 256, 256>>>(tab);

    gemm_tn<<<gg, 256, gsmem>>>(x, Wq, q, M_, C_, C_);
    gemm_tn<<<gg, 256, gsmem>>>(x, Wk, k, M_, C_, C_);
    gemm_tn<<<gg, 256, gsmem>>>(x, Wv, v, M_, C_, C_);

    const int pairs = M_ * (C_ / 2);
    rope_apply_kernel<<<(pairs + 255) / 256, 256>>>(q, k, tab);

    const int fsmem = 320 * FST * (int)sizeof(float);   // 87,040 B
    cudaFuncSetAttribute(flash_kernel,
                         cudaFuncAttributeMaxDynamicSharedMemorySize, fsmem);
    flash_kernel<<<dim3(T_ / 64, B_ * H_), 128, fsmem>>>(q, k, v, ob);

    gemm_tn<<<gg, 256, gsmem>>>(ob, Wo, out, M_, C_, C_);
}

// round 5
// speedup vs baseline: 1.8391x; 1.1297x over previous
#include <cuda_runtime.h>
#include <cuda_bf16.h>
#include <mma.h>
#include <math.h>

using namespace nvcuda;

#define B_  2
#define T_  2048
#define C_  1024
#define H_  16
#define D_  64
#define M_  (B_ * T_)   // 4096 rows

// ---------------- scratch (device globals: no allocation allowed) ----------
__device__ __align__(128) float g_q[(size_t)M_ * C_];
__device__ __align__(128) float g_k[(size_t)M_ * C_];
__device__ __align__(128) float g_v[(size_t)M_ * C_];
__device__ __align__(128) float g_o[(size_t)M_ * C_];
__device__ __align__(128) float g_xc[(size_t)M_ * C_];     // tf32-rounded x
__device__ __align__(128) float g_wc[4][(size_t)C_ * C_];  // tf32-rounded W
__device__ __align__(128) float2 g_rope_tab[T_ * 32];

// ---------------- helpers ----------------------------------------------------
__device__ __forceinline__ void cp16(void* smem_dst, const void* gmem_src) {
    unsigned s = (unsigned)__cvta_generic_to_shared(smem_dst);
    asm volatile("cp.async.cg.shared.global [%0], [%1], 16;\n"
                 :: "r"(s), "l"(gmem_src));
}
#define CP_COMMIT()  asm volatile("cp.async.commit_group;\n")
#define CP_WAIT(n)   asm volatile("cp.async.wait_group %0;\n" :: "n"(n))

__device__ __forceinline__ float tf32r(float f) {
    unsigned u;
    asm("cvt.rna.tf32.f32 %0, %1;" : "=r"(u) : "f"(f));
    return __uint_as_float(u);
}
__device__ __forceinline__ void mma8(float* d, const unsigned* a,
                                     const unsigned* b) {
    asm volatile(
        "mma.sync.aligned.m16n8k8.row.col.f32.tf32.tf32.f32 "
        "{%0,%1,%2,%3}, {%4,%5,%6,%7}, {%8,%9}, {%0,%1,%2,%3};"
        : "+f"(d[0]), "+f"(d[1]), "+f"(d[2]), "+f"(d[3])
        : "r"(a[0]), "r"(a[1]), "r"(a[2]), "r"(a[3]),
          "r"(b[0]), "r"(b[1]));
}

// ---------------------------------------------------------------------------
// tf32 pre-round pass (float4-vectorized)
// ---------------------------------------------------------------------------
__global__ __launch_bounds__(256) void round_kernel(
    const float* __restrict__ in, float* __restrict__ out, int n4)
{
    int i = blockIdx.x * blockDim.x + threadIdx.x;
    if (i >= n4) return;
    float4 t = ((const float4*)in)[i];
    t.x = tf32r(t.x); t.y = tf32r(t.y); t.z = tf32r(t.z); t.w = tf32r(t.w);
    ((float4*)out)[i] = t;
}

// ---------------------------------------------------------------------------
// GEMM: Y[M,N] = A[M,K] @ B[N,K]^T, tf32 wmma.
// Operands are PRE-ROUNDED to tf32 -> no CVT in the hot loop.
// 128x128 CTA tile, 4 warps (each 64x64), BK=32, cp.async double buffer,
// 2 CTAs/SM.
// ---------------------------------------------------------------------------
#define GST 36

__global__ __launch_bounds__(128, 2) void gemm_tn(
    const float* __restrict__ A, const float* __restrict__ Bm,
    float* __restrict__ Y, int M, int N, int K)
{
    extern __shared__ float sg[];
    float* As = sg;                    // 2 x 128 x GST
    float* Bs = sg + 2 * 128 * GST;    // 2 x 128 x GST

    const int m0  = blockIdx.y * 128;
    const int n0  = blockIdx.x * 128;
    const int tid = threadIdx.x;
    const int w   = tid >> 5;
    const int wm  = w >> 1;    // 0..1 -> 64-row strip
    const int wn  = w & 1;     // 0..1 -> 64-col strip

    wmma::fragment<wmma::accumulator, 16, 16, 8, float> acc[4][4];
#pragma unroll
    for (int i = 0; i < 4; i++)
#pragma unroll
        for (int j = 0; j < 4; j++) wmma::fill_fragment(acc[i][j], 0.0f);

    auto load_stage = [&](int buf, int kc) {
#pragma unroll
        for (int i = tid; i < 1024; i += 128) {
            int r = i >> 3;
            int c = (i & 7) << 2;
            cp16(&As[buf * 128 * GST + r * GST + c],
                 &A[(size_t)(m0 + r) * K + kc + c]);
            cp16(&Bs[buf * 128 * GST + r * GST + c],
                 &Bm[(size_t)(n0 + r) * K + kc + c]);
        }
    };

    load_stage(0, 0);
    CP_COMMIT();

    const int NIT = K / 32;
    for (int it = 0; it < NIT; it++) {
        if (it + 1 < NIT) {
            load_stage((it + 1) & 1, (it + 1) * 32);
            CP_COMMIT();
            CP_WAIT(1);
        } else {
            CP_WAIT(0);
        }
        __syncthreads();

        const float* Ab = &As[(it & 1) * 128 * GST];
        const float* Bb = &Bs[(it & 1) * 128 * GST];

#pragma unroll
        for (int k8 = 0; k8 < 4; k8++) {
            wmma::fragment<wmma::matrix_a, 16, 16, 8, wmma::precision::tf32,
                           wmma::row_major> a[4];
            wmma::fragment<wmma::matrix_b, 16, 16, 8, wmma::precision::tf32,
                           wmma::col_major> b[4];
#pragma unroll
            for (int i = 0; i < 4; i++)
                wmma::load_matrix_sync(a[i],
                    &Ab[(wm * 64 + i * 16) * GST + k8 * 8], GST);
#pragma unroll
            for (int j = 0; j < 4; j++)
                wmma::load_matrix_sync(b[j],
                    &Bb[(wn * 64 + j * 16) * GST + k8 * 8], GST);
#pragma unroll
            for (int i = 0; i < 4; i++)
#pragma unroll
                for (int j = 0; j < 4; j++)
                    wmma::mma_sync(acc[i][j], a[i], b[j], acc[i][j]);
        }
        __syncthreads();
    }

#pragma unroll
    for (int i = 0; i < 4; i++)
#pragma unroll
        for (int j = 0; j < 4; j++)
            wmma::store_matrix_sync(
                &Y[(size_t)(m0 + wm * 64 + i * 16) * N + n0 + wn * 64 + j * 16],
                acc[i][j], N, wmma::mem_row_major);
}

// ---------------------------------------------------------------------------
// RoPE table + apply. Apply also tf32-rounds q, k (post-rotation) and v.
// ---------------------------------------------------------------------------
__global__ __launch_bounds__(256) void rope_table_kernel(float2* __restrict__ tab)
{
    int idx = blockIdx.x * blockDim.x + threadIdx.x;
    if (idx >= T_ * 32) return;
    int t = idx >> 5;
    int j = idx & 31;
    double inv = exp(-((double)(2 * j) / 64.0) * log(10000.0));
    double ang = (double)t * inv;
    tab[idx] = make_float2((float)cos(ang), (float)sin(ang));
}

__global__ __launch_bounds__(256) void rope_apply_kernel(
    float* __restrict__ q, float* __restrict__ k, float* __restrict__ v,
    const float2* __restrict__ tab)
{
    int idx = blockIdx.x * blockDim.x + threadIdx.x;
    const int total = M_ * (C_ / 2);
    if (idx >= total) return;

    int row  = idx >> 9;
    int col2 = idx & 511;
    int t    = row & (T_ - 1);
    int j    = col2 & 31;
    int head = col2 >> 5;

    float2 cs = tab[t * 32 + j];
    size_t base = (size_t)row * C_ + head * D_ + 2 * j;

    float2 qv = *(float2*)&q[base];
    float2 kv = *(float2*)&k[base];
    float2 vv = *(float2*)&v[base];
    *(float2*)&q[base] = make_float2(tf32r(qv.x * cs.x - qv.y * cs.y),
                                     tf32r(qv.x * cs.y + qv.y * cs.x));
    *(float2*)&k[base] = make_float2(tf32r(kv.x * cs.x - kv.y * cs.y),
                                     tf32r(kv.x * cs.y + kv.y * cs.x));
    *(float2*)&v[base] = make_float2(tf32r(vv.x), tf32r(vv.y));
}

// ---------------------------------------------------------------------------
// Flash attention (causal), FA-2 style, operands pre-rounded tf32.
// BM=64 (4 warps x 16 rows), BN=64, D=64, mma.sync m16n8k8.
// ---------------------------------------------------------------------------
#define FST 68

__global__ __launch_bounds__(128, 2) void flash_kernel(
    const float* __restrict__ q, const float* __restrict__ k,
    const float* __restrict__ v, float* __restrict__ o)
{
    extern __shared__ float sm[];
    float* QP = sm;                   // 64*FST: Q staging, then P strips
    float* Kb = sm + 64 * FST;        // 2 x 64*FST
    float* Vb = sm + 192 * FST;       // 2 x 64*FST

    const int bh  = blockIdx.y;
    const int b   = bh >> 4;
    const int h   = bh & 15;
    const int q0  = (gridDim.x - 1 - blockIdx.x) * 64;
    const int tid = threadIdx.x;
    const int w   = tid >> 5;
    const int l   = tid & 31;
    const int g   = l >> 2;
    const int qd  = l & 3;
    const float scale = 0.125f;       // power of two: preserves tf32 exactness

    const size_t qrow = (size_t)(b * T_ + q0) * C_ + h * D_;

    auto kv_load = [&](int buf, int n0) {
        const size_t krow = (size_t)(b * T_ + n0) * C_ + h * D_;
#pragma unroll
        for (int i = tid; i < 1024; i += 128) {
            int r = i >> 4, c = (i & 15) << 2;
            cp16(&Kb[buf * 64 * FST + r * FST + c],
                 &k[krow + (size_t)r * C_ + c]);
            cp16(&Vb[buf * 64 * FST + r * FST + c],
                 &v[krow + (size_t)r * C_ + c]);
        }
    };

    kv_load(0, 0);
    CP_COMMIT();

    for (int i = tid; i < 1024; i += 128) {
        int r = i >> 4, c = (i & 15) << 2;
        float4 t4 = *(const float4*)&q[qrow + (size_t)r * C_ + c];
        t4.x *= scale; t4.y *= scale; t4.z *= scale; t4.w *= scale;
        *(float4*)&QP[r * FST + c] = t4;
    }
    __syncthreads();

    // Q fragments (already tf32-valid bits)
    unsigned aq[8][4];
    float* Pw = QP + w * 16 * FST;
#pragma unroll
    for (int kt = 0; kt < 8; kt++) {
        aq[kt][0] = __float_as_uint(Pw[g * FST + kt * 8 + qd]);
        aq[kt][1] = __float_as_uint(Pw[(g + 8) * FST + kt * 8 + qd]);
        aq[kt][2] = __float_as_uint(Pw[g * FST + kt * 8 + qd + 4]);
        aq[kt][3] = __float_as_uint(Pw[(g + 8) * FST + kt * 8 + qd + 4]);
    }
    __syncwarp();

    float oacc[8][4];
#pragma unroll
    for (int nt = 0; nt < 8; nt++)
#pragma unroll
        for (int j = 0; j < 4; j++) oacc[nt][j] = 0.0f;
    float mA = -INFINITY, mB = -INFINITY, lA = 0.0f, lB = 0.0f;

    const int rA_loc = w * 16 + g;
    const int rB_loc = rA_loc + 8;

    for (int n0 = 0; n0 <= q0; n0 += 64) {
        const int buf = (n0 >> 6) & 1;
        if (n0 + 64 <= q0) {
            kv_load(buf ^ 1, n0 + 64);
            CP_COMMIT();
            CP_WAIT(1);
        } else {
            CP_WAIT(0);
        }
        __syncthreads();

        const float* Ks = &Kb[buf * 64 * FST];
        const float* Vs = &Vb[buf * 64 * FST];

        float s[8][4];
#pragma unroll
        for (int nt = 0; nt < 8; nt++)
#pragma unroll
            for (int j = 0; j < 4; j++) s[nt][j] = 0.0f;

#pragma unroll
        for (int kt = 0; kt < 8; kt++) {
#pragma unroll
            for (int nt = 0; nt < 8; nt++) {
                unsigned bb[2];
                bb[0] = __float_as_uint(Ks[(nt * 8 + g) * FST + kt * 8 + qd]);
                bb[1] = __float_as_uint(Ks[(nt * 8 + g) * FST + kt * 8 + qd + 4]);
                mma8(s[nt], aq[kt], bb);
            }
        }

        if (n0 == q0) {
#pragma unroll
            for (int nt = 0; nt < 8; nt++) {
                int c0 = nt * 8 + 2 * qd;
                if (c0     > rA_loc) s[nt][0] = -INFINITY;
                if (c0 + 1 > rA_loc) s[nt][1] = -INFINITY;
                if (c0     > rB_loc) s[nt][2] = -INFINITY;
                if (c0 + 1 > rB_loc) s[nt][3] = -INFINITY;
            }
        }

        float mxA = -INFINITY, mxB = -INFINITY;
#pragma unroll
        for (int nt = 0; nt < 8; nt++) {
            mxA = fmaxf(mxA, fmaxf(s[nt][0], s[nt][1]));
            mxB = fmaxf(mxB, fmaxf(s[nt][2], s[nt][3]));
        }
        mxA = fmaxf(mxA, __shfl_xor_sync(0xffffffffu, mxA, 1));
        mxA = fmaxf(mxA, __shfl_xor_sync(0xffffffffu, mxA, 2));
        mxB = fmaxf(mxB, __shfl_xor_sync(0xffffffffu, mxB, 1));
        mxB = fmaxf(mxB, __shfl_xor_sync(0xffffffffu, mxB, 2));

        float nmA = fmaxf(mA, mxA);
        float nmB = fmaxf(mB, mxB);
        float alA = __expf(mA - nmA);
        float alB = __expf(mB - nmB);
        mA = nmA; mB = nmB;

        float sumA = 0.0f, sumB = 0.0f;
#pragma unroll
        for (int nt = 0; nt < 8; nt++) {
            float p0 = __expf(s[nt][0] - nmA);
            float p1 = __expf(s[nt][1] - nmA);
            float p2 = __expf(s[nt][2] - nmB);
            float p3 = __expf(s[nt][3] - nmB);
            s[nt][0] = p0; s[nt][1] = p1; s[nt][2] = p2; s[nt][3] = p3;
            sumA += p0 + p1;
            sumB += p2 + p3;
        }
        sumA += __shfl_xor_sync(0xffffffffu, sumA, 1);
        sumA += __shfl_xor_sync(0xffffffffu, sumA, 2);
        sumB += __shfl_xor_sync(0xffffffffu, sumB, 1);
        sumB += __shfl_xor_sync(0xffffffffu, sumB, 2);
        lA = lA * alA + sumA;
        lB = lB * alB + sumB;

#pragma unroll
        for (int nt = 0; nt < 8; nt++) {
            oacc[nt][0] *= alA; oacc[nt][1] *= alA;
            oacc[nt][2] *= alB; oacc[nt][3] *= alB;
        }

        // P (tf32-rounded at store) to warp-private strip
#pragma unroll
        for (int nt = 0; nt < 8; nt++) {
            *(float2*)&Pw[g * FST + nt * 8 + 2 * qd] =
                make_float2(tf32r(s[nt][0]), tf32r(s[nt][1]));
            *(float2*)&Pw[(g + 8) * FST + nt * 8 + 2 * qd] =
                make_float2(tf32r(s[nt][2]), tf32r(s[nt][3]));
        }
        __syncwarp();

#pragma unroll
        for (int kt = 0; kt < 8; kt++) {
            unsigned ap[4];
            ap[0] = __float_as_uint(Pw[g * FST + kt * 8 + qd]);
            ap[1] = __float_as_uint(Pw[(g + 8) * FST + kt * 8 + qd]);
            ap[2] = __float_as_uint(Pw[g * FST + kt * 8 + qd + 4]);
            ap[3] = __float_as_uint(Pw[(g + 8) * FST + kt * 8 + qd + 4]);
#pragma unroll
            for (int nt = 0; nt < 8; nt++) {
                unsigned bb[2];
                bb[0] = __float_as_uint(Vs[(kt * 8 + qd) * FST + nt * 8 + g]);
                bb[1] = __float_as_uint(Vs[(kt * 8 + qd + 4) * FST + nt * 8 + g]);
                mma8(oacc[nt], ap, bb);
            }
        }
        __syncthreads();
    }

    // normalize + write, tf32-rounded so the Wo GEMM reads valid tf32 bits
    const float rA = 1.0f / lA;
    const float rB = 1.0f / lB;
#pragma unroll
    for (int nt = 0; nt < 8; nt++) {
        int c0 = nt * 8 + 2 * qd;
        *(float2*)&o[qrow + (size_t)rA_loc * C_ + c0] =
            make_float2(tf32r(oacc[nt][0] * rA), tf32r(oacc[nt][1] * rA));
        *(float2*)&o[qrow + (size_t)rB_loc * C_ + c0] =
            make_float2(tf32r(oacc[nt][2] * rB), tf32r(oacc[nt][3] * rB));
    }
}

// ---------------------------------------------------------------------------
extern "C" void kernel_launch(void* const* d_in, const int* in_sizes, int n_in,
                              void* d_out, int out_size)
{
    (void)in_sizes; (void)n_in; (void)out_size;
    const float* x  = (const float*)d_in[0];
    const float* Wq = (const float*)d_in[1];
    const float* Wk = (const float*)d_in[2];
    const float* Wv = (const float*)d_in[3];
    const float* Wo = (const float*)d_in[4];
    float* out = (float*)d_out;

    float *q, *k, *v, *ob, *xc, *wc;
    float2* tab;
    cudaGetSymbolAddress((void**)&q,   g_q);
    cudaGetSymbolAddress((void**)&k,   g_k);
    cudaGetSymbolAddress((void**)&v,   g_v);
    cudaGetSymbolAddress((void**)&ob,  g_o);
    cudaGetSymbolAddress((void**)&xc,  g_xc);
    cudaGetSymbolAddress((void**)&wc,  g_wc);
    cudaGetSymbolAddress((void**)&tab, g_rope_tab);

    float* wqc = wc;
    float* wkc = wc + (size_t)C_ * C_;
    float* wvc = wc + 2 * (size_t)C_ * C_;
    float* woc = wc + 3 * (size_t)C_ * C_;

    // pre-round operands to tf32
    const int xn4 = M_ * C_ / 4, wn4 = C_ * C_ / 4;
    round_kernel<<<(xn4 + 255) / 256, 256>>>(x,  xc,  xn4);
    round_kernel<<<(wn4 + 255) / 256, 256>>>(Wq, wqc, wn4);
    round_kernel<<<(wn4 + 255) / 256, 256>>>(Wk, wkc, wn4);
    round_kernel<<<(wn4 + 255) / 256, 256>>>(Wv, wvc, wn4);
    round_kernel<<<(wn4 + 255) / 256, 256>>>(Wo, woc, wn4);
    rope_table_kernel<<<(T_ * 32 + 255) / 256, 256>>>(tab);

    const int gsmem = 4 * 128 * GST * (int)sizeof(float);   // 73,728 B
    cudaFuncSetAttribute(gemm_tn,
                         cudaFuncAttributeMaxDynamicSharedMemorySize, gsmem);
    const dim3 gg(C_ / 128, M_ / 128);   // (8, 32)

    gemm_tn<<<gg, 128, gsmem>>>(xc, wqc, q, M_, C_, C_);
    gemm_tn<<<gg, 128, gsmem>>>(xc, wkc, k, M_, C_, C_);
    gemm_tn<<<gg, 128, gsmem>>>(xc, wvc, v, M_, C_, C_);

    const int pairs = M_ * (C_ / 2);
    rope_apply_kernel<<<(pairs + 255) / 256, 256>>>(q, k, v, tab);

    const int fsmem = 320 * FST * (int)sizeof(float);   // 87,040 B
    cudaFuncSetAttribute(flash_kernel,
                         cudaFuncAttributeMaxDynamicSharedMemorySize, fsmem);
    flash_kernel<<<dim3(T_ / 64, B_ * H_), 128, fsmem>>>(q, k, v, ob);

    gemm_tn<<<gg, 128, gsmem>>>(ob, woc, out, M_, C_, C_);
}

// round 6
// speedup vs baseline: 1.8502x; 1.0060x over previous
#include <cuda_runtime.h>
#include <cuda_bf16.h>
#include <mma.h>
#include <math.h>

using namespace nvcuda;

#define B_  2
#define T_  2048
#define C_  1024
#define H_  16
#define D_  64
#define M_  (B_ * T_)     // 4096 rows
#define N3  (3 * C_)      // fused QKV width

// ---------------- scratch (device globals: no allocation allowed) ----------
__device__ __align__(128) float g_qkv[(size_t)M_ * N3];    // fused q|k|v
__device__ __align__(128) float g_o[(size_t)M_ * C_];
__device__ __align__(128) float g_xc[(size_t)M_ * C_];     // tf32-rounded x
__device__ __align__(128) float g_wc[4][(size_t)C_ * C_];  // tf32 Wq|Wk|Wv|Wo
__device__ __align__(128) float2 g_rope_tab[T_ * 32];

// ---------------- helpers ----------------------------------------------------
__device__ __forceinline__ void cp16(void* smem_dst, const void* gmem_src) {
    unsigned s = (unsigned)__cvta_generic_to_shared(smem_dst);
    asm volatile("cp.async.cg.shared.global [%0], [%1], 16;\n"
                 :: "r"(s), "l"(gmem_src));
}
#define CP_COMMIT()  asm volatile("cp.async.commit_group;\n")
#define CP_WAIT(n)   asm volatile("cp.async.wait_group %0;\n" :: "n"(n))

__device__ __forceinline__ float tf32r(float f) {
    unsigned u;
    asm("cvt.rna.tf32.f32 %0, %1;" : "=r"(u) : "f"(f));
    return __uint_as_float(u);
}
__device__ __forceinline__ void mma8(float* d, const unsigned* a,
                                     const unsigned* b) {
    asm volatile(
        "mma.sync.aligned.m16n8k8.row.col.f32.tf32.tf32.f32 "
        "{%0,%1,%2,%3}, {%4,%5,%6,%7}, {%8,%9}, {%0,%1,%2,%3};"
        : "+f"(d[0]), "+f"(d[1]), "+f"(d[2]), "+f"(d[3])
        : "r"(a[0]), "r"(a[1]), "r"(a[2]), "r"(a[3]),
          "r"(b[0]), "r"(b[1]));
}

// ---------------------------------------------------------------------------
// tf32 pre-round pass
// ---------------------------------------------------------------------------
__global__ __launch_bounds__(256) void round_kernel(
    const float* __restrict__ in, float* __restrict__ out, int n4)
{
    int i = blockIdx.x * blockDim.x + threadIdx.x;
    if (i >= n4) return;
    float4 t = ((const float4*)in)[i];
    t.x = tf32r(t.x); t.y = tf32r(t.y); t.z = tf32r(t.z); t.w = tf32r(t.w);
    ((float4*)out)[i] = t;
}

// ---------------------------------------------------------------------------
// GEMM: Y[M,N] = A[M,K] @ B[N,K]^T, tf32 wmma, pre-rounded operands.
// 128x128 CTA tile, 4 warps (64x64 each), BK=32, 3-stage cp.async pipeline,
// 2 CTAs/SM.
// ---------------------------------------------------------------------------
#define GST 36

__global__ __launch_bounds__(128, 2) void gemm_tn(
    const float* __restrict__ A, const float* __restrict__ Bm,
    float* __restrict__ Y, int M, int N, int K)
{
    extern __shared__ float sg[];
    float* As = sg;                    // 3 x 128 x GST
    float* Bs = sg + 3 * 128 * GST;    // 3 x 128 x GST

    const int m0  = blockIdx.y * 128;
    const int n0  = blockIdx.x * 128;
    const int tid = threadIdx.x;
    const int w   = tid >> 5;
    const int wm  = w >> 1;
    const int wn  = w & 1;

    wmma::fragment<wmma::accumulator, 16, 16, 8, float> acc[4][4];
#pragma unroll
    for (int i = 0; i < 4; i++)
#pragma unroll
        for (int j = 0; j < 4; j++) wmma::fill_fragment(acc[i][j], 0.0f);

    auto load_stage = [&](int buf, int kc) {
#pragma unroll
        for (int i = tid; i < 1024; i += 128) {
            int r = i >> 3;
            int c = (i & 7) << 2;
            cp16(&As[buf * 128 * GST + r * GST + c],
                 &A[(size_t)(m0 + r) * K + kc + c]);
            cp16(&Bs[buf * 128 * GST + r * GST + c],
                 &Bm[(size_t)(n0 + r) * K + kc + c]);
        }
    };

    load_stage(0, 0);
    CP_COMMIT();
    load_stage(1, 32);
    CP_COMMIT();

    const int NIT = K / 32;
    int buf = 0;
    for (int it = 0; it < NIT; it++) {
        if (it + 2 < NIT) {
            load_stage((buf + 2) % 3, (it + 2) * 32);
            CP_COMMIT();
            CP_WAIT(2);
        } else if (it + 1 < NIT) {
            CP_WAIT(1);
        } else {
            CP_WAIT(0);
        }
        __syncthreads();

        const float* Ab = &As[buf * 128 * GST];
        const float* Bb = &Bs[buf * 128 * GST];

#pragma unroll
        for (int k8 = 0; k8 < 4; k8++) {
            wmma::fragment<wmma::matrix_a, 16, 16, 8, wmma::precision::tf32,
                           wmma::row_major> a[4];
            wmma::fragment<wmma::matrix_b, 16, 16, 8, wmma::precision::tf32,
                           wmma::col_major> b[4];
#pragma unroll
            for (int i = 0; i < 4; i++)
                wmma::load_matrix_sync(a[i],
                    &Ab[(wm * 64 + i * 16) * GST + k8 * 8], GST);
#pragma unroll
            for (int j = 0; j < 4; j++)
                wmma::load_matrix_sync(b[j],
                    &Bb[(wn * 64 + j * 16) * GST + k8 * 8], GST);
#pragma unroll
            for (int i = 0; i < 4; i++)
#pragma unroll
                for (int j = 0; j < 4; j++)
                    wmma::mma_sync(acc[i][j], a[i], b[j], acc[i][j]);
        }
        __syncthreads();
        buf = (buf + 1) % 3;
    }

#pragma unroll
    for (int i = 0; i < 4; i++)
#pragma unroll
        for (int j = 0; j < 4; j++)
            wmma::store_matrix_sync(
                &Y[(size_t)(m0 + wm * 64 + i * 16) * N + n0 + wn * 64 + j * 16],
                acc[i][j], N, wmma::mem_row_major);
}

// ---------------------------------------------------------------------------
// RoPE table + apply (on fused qkv buffer; also tf32-rounds v).
// ---------------------------------------------------------------------------
__global__ __launch_bounds__(256) void rope_table_kernel(float2* __restrict__ tab)
{
    int idx = blockIdx.x * blockDim.x + threadIdx.x;
    if (idx >= T_ * 32) return;
    int t = idx >> 5;
    int j = idx & 31;
    double inv = exp(-((double)(2 * j) / 64.0) * log(10000.0));
    double ang = (double)t * inv;
    tab[idx] = make_float2((float)cos(ang), (float)sin(ang));
}

__global__ __launch_bounds__(256) void rope_apply_kernel(
    float* __restrict__ qkv, const float2* __restrict__ tab)
{
    int idx = blockIdx.x * blockDim.x + threadIdx.x;
    const int total = M_ * (C_ / 2);
    if (idx >= total) return;

    int row  = idx >> 9;
    int col2 = idx & 511;
    int t    = row & (T_ - 1);
    int j    = col2 & 31;
    int head = col2 >> 5;

    float2 cs = tab[t * 32 + j];
    size_t base = (size_t)row * N3 + head * D_ + 2 * j;

    float2 qv = *(float2*)&qkv[base];
    float2 kv = *(float2*)&qkv[base + C_];
    float2 vv = *(float2*)&qkv[base + 2 * C_];
    *(float2*)&qkv[base] =
        make_float2(tf32r(qv.x * cs.x - qv.y * cs.y),
                    tf32r(qv.x * cs.y + qv.y * cs.x));
    *(float2*)&qkv[base + C_] =
        make_float2(tf32r(kv.x * cs.x - kv.y * cs.y),
                    tf32r(kv.x * cs.y + kv.y * cs.x));
    *(float2*)&qkv[base + 2 * C_] = make_float2(tf32r(vv.x), tf32r(vv.y));
}

// ---------------------------------------------------------------------------
// Flash attention (causal), FA-2 style, fused-qkv input (row stride N3).
// BM=64 (4 warps x 16 rows), BN=64, D=64, mma.sync m16n8k8 tf32.
// ---------------------------------------------------------------------------
#define FST 68

__global__ __launch_bounds__(128, 2) void flash_kernel(
    const float* __restrict__ qkv, float* __restrict__ o)
{
    extern __shared__ float sm[];
    float* QP = sm;                   // 64*FST: Q staging, then P strips
    float* Kb = sm + 64 * FST;        // 2 x 64*FST
    float* Vb = sm + 192 * FST;       // 2 x 64*FST

    const int bh  = blockIdx.y;
    const int b   = bh >> 4;
    const int h   = bh & 15;
    const int q0  = (gridDim.x - 1 - blockIdx.x) * 64;
    const int tid = threadIdx.x;
    const int w   = tid >> 5;
    const int l   = tid & 31;
    const int g   = l >> 2;
    const int qd  = l & 3;
    const float scale = 0.125f;

    const size_t qbase = (size_t)(b * T_ + q0) * N3 + h * D_;
    const size_t orow  = (size_t)(b * T_ + q0) * C_ + h * D_;

    auto kv_load = [&](int buf, int n0) {
        const size_t kbase = (size_t)(b * T_ + n0) * N3 + h * D_ + C_;
#pragma unroll
        for (int i = tid; i < 1024; i += 128) {
            int r = i >> 4, c = (i & 15) << 2;
            cp16(&Kb[buf * 64 * FST + r * FST + c],
                 &qkv[kbase + (size_t)r * N3 + c]);
            cp16(&Vb[buf * 64 * FST + r * FST + c],
                 &qkv[kbase + (size_t)r * N3 + C_ + c]);
        }
    };

    kv_load(0, 0);
    CP_COMMIT();

    for (int i = tid; i < 1024; i += 128) {
        int r = i >> 4, c = (i & 15) << 2;
        float4 t4 = *(const float4*)&qkv[qbase + (size_t)r * N3 + c];
        t4.x *= scale; t4.y *= scale; t4.z *= scale; t4.w *= scale;
        *(float4*)&QP[r * FST + c] = t4;
    }
    __syncthreads();

    unsigned aq[8][4];
    float* Pw = QP + w * 16 * FST;
#pragma unroll
    for (int kt = 0; kt < 8; kt++) {
        aq[kt][0] = __float_as_uint(Pw[g * FST + kt * 8 + qd]);
        aq[kt][1] = __float_as_uint(Pw[(g + 8) * FST + kt * 8 + qd]);
        aq[kt][2] = __float_as_uint(Pw[g * FST + kt * 8 + qd + 4]);
        aq[kt][3] = __float_as_uint(Pw[(g + 8) * FST + kt * 8 + qd + 4]);
    }
    __syncwarp();

    float oacc[8][4];
#pragma unroll
    for (int nt = 0; nt < 8; nt++)
#pragma unroll
        for (int j = 0; j < 4; j++) oacc[nt][j] = 0.0f;
    float mA = -INFINITY, mB = -INFINITY, lA = 0.0f, lB = 0.0f;

    const int rA_loc = w * 16 + g;
    const int rB_loc = rA_loc + 8;

    for (int n0 = 0; n0 <= q0; n0 += 64) {
        const int buf = (n0 >> 6) & 1;
        if (n0 + 64 <= q0) {
            kv_load(buf ^ 1, n0 + 64);
            CP_COMMIT();
            CP_WAIT(1);
        } else {
            CP_WAIT(0);
        }
        __syncthreads();

        const float* Ks = &Kb[buf * 64 * FST];
        const float* Vs = &Vb[buf * 64 * FST];

        float s[8][4];
#pragma unroll
        for (int nt = 0; nt < 8; nt++)
#pragma unroll
            for (int j = 0; j < 4; j++) s[nt][j] = 0.0f;

#pragma unroll
        for (int kt = 0; kt < 8; kt++) {
#pragma unroll
            for (int nt = 0; nt < 8; nt++) {
                unsigned bb[2];
                bb[0] = __float_as_uint(Ks[(nt * 8 + g) * FST + kt * 8 + qd]);
                bb[1] = __float_as_uint(Ks[(nt * 8 + g) * FST + kt * 8 + qd + 4]);
                mma8(s[nt], aq[kt], bb);
            }
        }

        if (n0 == q0) {
#pragma unroll
            for (int nt = 0; nt < 8; nt++) {
                int c0 = nt * 8 + 2 * qd;
                if (c0     > rA_loc) s[nt][0] = -INFINITY;
                if (c0 + 1 > rA_loc) s[nt][1] = -INFINITY;
                if (c0     > rB_loc) s[nt][2] = -INFINITY;
                if (c0 + 1 > rB_loc) s[nt][3] = -INFINITY;
            }
        }

        float mxA = -INFINITY, mxB = -INFINITY;
#pragma unroll
        for (int nt = 0; nt < 8; nt++) {
            mxA = fmaxf(mxA, fmaxf(s[nt][0], s[nt][1]));
            mxB = fmaxf(mxB, fmaxf(s[nt][2], s[nt][3]));
        }
        mxA = fmaxf(mxA, __shfl_xor_sync(0xffffffffu, mxA, 1));
        mxA = fmaxf(mxA, __shfl_xor_sync(0xffffffffu, mxA, 2));
        mxB = fmaxf(mxB, __shfl_xor_sync(0xffffffffu, mxB, 1));
        mxB = fmaxf(mxB, __shfl_xor_sync(0xffffffffu, mxB, 2));

        float nmA = fmaxf(mA, mxA);
        float nmB = fmaxf(mB, mxB);
        float alA = __expf(mA - nmA);
        float alB = __expf(mB - nmB);
        mA = nmA; mB = nmB;

        float sumA = 0.0f, sumB = 0.0f;
#pragma unroll
        for (int nt = 0; nt < 8; nt++) {
            float p0 = __expf(s[nt][0] - nmA);
            float p1 = __expf(s[nt][1] - nmA);
            float p2 = __expf(s[nt][2] - nmB);
            float p3 = __expf(s[nt][3] - nmB);
            s[nt][0] = p0; s[nt][1] = p1; s[nt][2] = p2; s[nt][3] = p3;
            sumA += p0 + p1;
            sumB += p2 + p3;
        }
        sumA += __shfl_xor_sync(0xffffffffu, sumA, 1);
        sumA += __shfl_xor_sync(0xffffffffu, sumA, 2);
        sumB += __shfl_xor_sync(0xffffffffu, sumB, 1);
        sumB += __shfl_xor_sync(0xffffffffu, sumB, 2);
        lA = lA * alA + sumA;
        lB = lB * alB + sumB;

#pragma unroll
        for (int nt = 0; nt < 8; nt++) {
            oacc[nt][0] *= alA; oacc[nt][1] *= alA;
            oacc[nt][2] *= alB; oacc[nt][3] *= alB;
        }

#pragma unroll
        for (int nt = 0; nt < 8; nt++) {
            *(float2*)&Pw[g * FST + nt * 8 + 2 * qd] =
                make_float2(tf32r(s[nt][0]), tf32r(s[nt][1]));
            *(float2*)&Pw[(g + 8) * FST + nt * 8 + 2 * qd] =
                make_float2(tf32r(s[nt][2]), tf32r(s[nt][3]));
        }
        __syncwarp();

#pragma unroll
        for (int kt = 0; kt < 8; kt++) {
            unsigned ap[4];
            ap[0] = __float_as_uint(Pw[g * FST + kt * 8 + qd]);
            ap[1] = __float_as_uint(Pw[(g + 8) * FST + kt * 8 + qd]);
            ap[2] = __float_as_uint(Pw[g * FST + kt * 8 + qd + 4]);
            ap[3] = __float_as_uint(Pw[(g + 8) * FST + kt * 8 + qd + 4]);
#pragma unroll
            for (int nt = 0; nt < 8; nt++) {
                unsigned bb[2];
                bb[0] = __float_as_uint(Vs[(kt * 8 + qd) * FST + nt * 8 + g]);
                bb[1] = __float_as_uint(Vs[(kt * 8 + qd + 4) * FST + nt * 8 + g]);
                mma8(oacc[nt], ap, bb);
            }
        }
        __syncthreads();
    }

    const float rA = 1.0f / lA;
    const float rB = 1.0f / lB;
#pragma unroll
    for (int nt = 0; nt < 8; nt++) {
        int c0 = nt * 8 + 2 * qd;
        *(float2*)&o[orow + (size_t)rA_loc * C_ + c0] =
            make_float2(tf32r(oacc[nt][0] * rA), tf32r(oacc[nt][1] * rA));
        *(float2*)&o[orow + (size_t)rB_loc * C_ + c0] =
            make_float2(tf32r(oacc[nt][2] * rB), tf32r(oacc[nt][3] * rB));
    }
}

// ---------------------------------------------------------------------------
extern "C" void kernel_launch(void* const* d_in, const int* in_sizes, int n_in,
                              void* d_out, int out_size)
{
    (void)in_sizes; (void)n_in; (void)out_size;
    const float* x  = (const float*)d_in[0];
    const float* Wq = (const float*)d_in[1];
    const float* Wk = (const float*)d_in[2];
    const float* Wv = (const float*)d_in[3];
    const float* Wo = (const float*)d_in[4];
    float* out = (float*)d_out;

    float *qkv, *ob, *xc, *wc;
    float2* tab;
    cudaGetSymbolAddress((void**)&qkv, g_qkv);
    cudaGetSymbolAddress((void**)&ob,  g_o);
    cudaGetSymbolAddress((void**)&xc,  g_xc);
    cudaGetSymbolAddress((void**)&wc,  g_wc);
    cudaGetSymbolAddress((void**)&tab, g_rope_tab);

    float* wqkv = wc;                          // [3C][C], contiguous
    float* woc  = wc + 3 * (size_t)C_ * C_;

    const int xn4 = M_ * C_ / 4, wn4 = C_ * C_ / 4;
    round_kernel<<<(xn4 + 255) / 256, 256>>>(x,  xc, xn4);
    round_kernel<<<(wn4 + 255) / 256, 256>>>(Wq, wqkv,                       wn4);
    round_kernel<<<(wn4 + 255) / 256, 256>>>(Wk, wqkv + (size_t)C_ * C_,     wn4);
    round_kernel<<<(wn4 + 255) / 256, 256>>>(Wv, wqkv + 2 * (size_t)C_ * C_, wn4);
    round_kernel<<<(wn4 + 255) / 256, 256>>>(Wo, woc,                        wn4);
    rope_table_kernel<<<(T_ * 32 + 255) / 256, 256>>>(tab);

    const int gsmem = 6 * 128 * GST * (int)sizeof(float);   // 110,592 B
    cudaFuncSetAttribute(gemm_tn,
                         cudaFuncAttributeMaxDynamicSharedMemorySize, gsmem);

    // fused QKV projection: Y[M, 3C] = x @ [Wq;Wk;Wv]^T
    gemm_tn<<<dim3(N3 / 128, M_ / 128), 128, gsmem>>>(xc, wqkv, qkv,
                                                      M_, N3, C_);

    const int pairs = M_ * (C_ / 2);
    rope_apply_kernel<<<(pairs + 255) / 256, 256>>>(qkv, tab);

    const int fsmem = 320 * FST * (int)sizeof(float);   // 87,040 B
    cudaFuncSetAttribute(flash_kernel,
                         cudaFuncAttributeMaxDynamicSharedMemorySize, fsmem);
    flash_kernel<<<dim3(T_ / 64, B_ * H_), 128, fsmem>>>(qkv, ob);

    gemm_tn<<<dim3(C_ / 128, M_ / 128), 128, gsmem>>>(ob, woc, out,
                                                      M_, C_, C_);
}

// round 7
// speedup vs baseline: 3.0052x; 1.6243x over previous
#include <cuda_runtime.h>
#include <cuda_bf16.h>
#include <math.h>

#define B_  2
#define T_  2048
#define C_  1024
#define H_  16
#define D_  64
#define M_  (B_ * T_)     // 4096 rows
#define N3  (3 * C_)      // fused QKV width

// ---------------- scratch (device globals: no allocation allowed) ----------
__device__ __align__(128) float g_qkv[(size_t)M_ * N3];    // fused q|k|v
__device__ __align__(128) float g_o[(size_t)M_ * C_];
__device__ __align__(128) float g_xc[(size_t)M_ * C_];     // tf32-rounded x
__device__ __align__(128) float g_wc[4][(size_t)C_ * C_];  // tf32 Wq|Wk|Wv|Wo
__device__ __align__(128) float2 g_rope_tab[T_ * 32];

// ---------------- helpers ----------------------------------------------------
__device__ __forceinline__ void cp16(void* smem_dst, const void* gmem_src) {
    unsigned s = (unsigned)__cvta_generic_to_shared(smem_dst);
    asm volatile("cp.async.cg.shared.global [%0], [%1], 16;\n"
                 :: "r"(s), "l"(gmem_src));
}
#define CP_COMMIT()  asm volatile("cp.async.commit_group;\n")
#define CP_WAIT(n)   asm volatile("cp.async.wait_group %0;\n" :: "n"(n))

__device__ __forceinline__ float tf32r(float f) {
    unsigned u;
    asm("cvt.rna.tf32.f32 %0, %1;" : "=r"(u) : "f"(f));
    return __uint_as_float(u);
}
__device__ __forceinline__ void mma8(float* d, const unsigned* a,
                                     const unsigned* b) {
    asm volatile(
        "mma.sync.aligned.m16n8k8.row.col.f32.tf32.tf32.f32 "
        "{%0,%1,%2,%3}, {%4,%5,%6,%7}, {%8,%9}, {%0,%1,%2,%3};"
        : "+f"(d[0]), "+f"(d[1]), "+f"(d[2]), "+f"(d[3])
        : "r"(a[0]), "r"(a[1]), "r"(a[2]), "r"(a[3]),
          "r"(b[0]), "r"(b[1]));
}

// ---------------------------------------------------------------------------
// tf32 pre-round pass
// ---------------------------------------------------------------------------
__global__ __launch_bounds__(256) void round_kernel(
    const float* __restrict__ in, float* __restrict__ out, int n4)
{
    int i = blockIdx.x * blockDim.x + threadIdx.x;
    if (i >= n4) return;
    float4 t = ((const float4*)in)[i];
    t.x = tf32r(t.x); t.y = tf32r(t.y); t.z = tf32r(t.z); t.w = tf32r(t.w);
    ((float4*)out)[i] = t;
}

// ---------------------------------------------------------------------------
// GEMM: Y[M,N] = A[M,K] @ B[N,K]^T, raw mma.sync m16n8k8 tf32.
// 128x128 CTA tile, 4 warps (64x64 each), BK=32, 3-stage cp.async,
// ONE __syncthreads per K-iteration, 2 CTAs/SM. Operands pre-rounded tf32.
// ---------------------------------------------------------------------------
#define GST 36

__global__ __launch_bounds__(128, 2) void gemm_tn(
    const float* __restrict__ A, const float* __restrict__ Bm,
    float* __restrict__ Y, int M, int N, int K)
{
    extern __shared__ float sg[];
    float* As = sg;                    // 3 x 128 x GST
    float* Bs = sg + 3 * 128 * GST;    // 3 x 128 x GST

    const int m0  = blockIdx.y * 128;
    const int n0  = blockIdx.x * 128;
    const int tid = threadIdx.x;
    const int w   = tid >> 5;
    const int wm  = w >> 1;     // 64-row strip
    const int wn  = w & 1;      // 64-col strip
    const int l   = tid & 31;
    const int g   = l >> 2;
    const int qd  = l & 3;

    float acc[4][8][4];   // [m16 tile][n8 tile][frag] = 128 regs
#pragma unroll
    for (int i = 0; i < 4; i++)
#pragma unroll
        for (int j = 0; j < 8; j++)
#pragma unroll
            for (int e = 0; e < 4; e++) acc[i][j][e] = 0.0f;

    auto load_stage = [&](int buf, int kc) {
#pragma unroll
        for (int i = tid; i < 1024; i += 128) {
            int r = i >> 3;
            int c = (i & 7) << 2;
            cp16(&As[buf * 128 * GST + r * GST + c],
                 &A[(size_t)(m0 + r) * K + kc + c]);
            cp16(&Bs[buf * 128 * GST + r * GST + c],
                 &Bm[(size_t)(n0 + r) * K + kc + c]);
        }
    };

    load_stage(0, 0);
    CP_COMMIT();
    load_stage(1, 32);
    CP_COMMIT();

    const int NIT = K / 32;
    for (int it = 0; it < NIT; it++) {
        if (it < NIT - 1) { CP_WAIT(1); } else { CP_WAIT(0); }
        __syncthreads();
        if (it + 2 < NIT) {
            load_stage((it + 2) % 3, (it + 2) * 32);
            CP_COMMIT();
        }

        const float* Ab = &As[(it % 3) * 128 * GST + (wm * 64) * GST];
        const float* Bb = &Bs[(it % 3) * 128 * GST + (wn * 64) * GST];

#pragma unroll
        for (int k8 = 0; k8 < 4; k8++) {
            unsigned av[4][4];
#pragma unroll
            for (int i = 0; i < 4; i++) {
                av[i][0] = __float_as_uint(Ab[(i * 16 + g)     * GST + k8 * 8 + qd]);
                av[i][1] = __float_as_uint(Ab[(i * 16 + g + 8) * GST + k8 * 8 + qd]);
                av[i][2] = __float_as_uint(Ab[(i * 16 + g)     * GST + k8 * 8 + qd + 4]);
                av[i][3] = __float_as_uint(Ab[(i * 16 + g + 8) * GST + k8 * 8 + qd + 4]);
            }
            unsigned bv[8][2];
#pragma unroll
            for (int j = 0; j < 8; j++) {
                bv[j][0] = __float_as_uint(Bb[(j * 8 + g) * GST + k8 * 8 + qd]);
                bv[j][1] = __float_as_uint(Bb[(j * 8 + g) * GST + k8 * 8 + qd + 4]);
            }
#pragma unroll
            for (int i = 0; i < 4; i++)
#pragma unroll
                for (int j = 0; j < 8; j++)
                    mma8(acc[i][j], av[i], bv[j]);
        }
    }

    // epilogue: float2 stores (c0,c1 are adjacent cols; c2,c3 row+8)
#pragma unroll
    for (int i = 0; i < 4; i++) {
        const size_t rowA = (size_t)(m0 + wm * 64 + i * 16 + g) * N;
        const size_t rowB = rowA + 8 * N;
#pragma unroll
        for (int j = 0; j < 8; j++) {
            const int col = n0 + wn * 64 + j * 8 + 2 * qd;
            *(float2*)&Y[rowA + col] = make_float2(acc[i][j][0], acc[i][j][1]);
            *(float2*)&Y[rowB + col] = make_float2(acc[i][j][2], acc[i][j][3]);
        }
    }
}

// ---------------------------------------------------------------------------
// RoPE table + apply (fused qkv buffer; also tf32-rounds v)
// ---------------------------------------------------------------------------
__global__ __launch_bounds__(256) void rope_table_kernel(float2* __restrict__ tab)
{
    int idx = blockIdx.x * blockDim.x + threadIdx.x;
    if (idx >= T_ * 32) return;
    int t = idx >> 5;
    int j = idx & 31;
    double inv = exp(-((double)(2 * j) / 64.0) * log(10000.0));
    double ang = (double)t * inv;
    tab[idx] = make_float2((float)cos(ang), (float)sin(ang));
}

__global__ __launch_bounds__(256) void rope_apply_kernel(
    float* __restrict__ qkv, const float2* __restrict__ tab)
{
    int idx = blockIdx.x * blockDim.x + threadIdx.x;
    const int total = M_ * (C_ / 2);
    if (idx >= total) return;

    int row  = idx >> 9;
    int col2 = idx & 511;
    int t    = row & (T_ - 1);
    int j    = col2 & 31;
    int head = col2 >> 5;

    float2 cs = tab[t * 32 + j];
    size_t base = (size_t)row * N3 + head * D_ + 2 * j;

    float2 qv = *(float2*)&qkv[base];
    float2 kv = *(float2*)&qkv[base + C_];
    float2 vv = *(float2*)&qkv[base + 2 * C_];
    *(float2*)&qkv[base] =
        make_float2(tf32r(qv.x * cs.x - qv.y * cs.y),
                    tf32r(qv.x * cs.y + qv.y * cs.x));
    *(float2*)&qkv[base + C_] =
        make_float2(tf32r(kv.x * cs.x - kv.y * cs.y),
                    tf32r(kv.x * cs.y + kv.y * cs.x));
    *(float2*)&qkv[base + 2 * C_] = make_float2(tf32r(vv.x), tf32r(vv.y));
}

// ---------------------------------------------------------------------------
// Flash attention (causal), FA-2 style, fused-qkv input (row stride N3).
// BM=64 (4 warps x 16 rows), BN=64, D=64, mma.sync m16n8k8 tf32.
// ONE __syncthreads per KV tile. V uses stride 72 (conflict-free PV loads),
// K/Q/P use stride 68 (conflict-free S loads).
// ---------------------------------------------------------------------------
#define FST 68
#define VST 72

__global__ __launch_bounds__(128, 2) void flash_kernel(
    const float* __restrict__ qkv, float* __restrict__ o)
{
    extern __shared__ float sm[];
    float* QP = sm;                     // 64*FST: Q staging, then P strips
    float* Kb = QP + 64 * FST;          // 2 x 64*FST
    float* Vb = Kb + 128 * FST;         // 2 x 64*VST

    const int bh  = blockIdx.y;
    const int b   = bh >> 4;
    const int h   = bh & 15;
    const int q0  = (gridDim.x - 1 - blockIdx.x) * 64;
    const int tid = threadIdx.x;
    const int w   = tid >> 5;
    const int l   = tid & 31;
    const int g   = l >> 2;
    const int qd  = l & 3;
    const float scale = 0.125f;

    const size_t qbase = (size_t)(b * T_ + q0) * N3 + h * D_;
    const size_t orow  = (size_t)(b * T_ + q0) * C_ + h * D_;

    auto kv_load = [&](int buf, int n0) {
        const size_t kbase = (size_t)(b * T_ + n0) * N3 + h * D_ + C_;
#pragma unroll
        for (int i = tid; i < 1024; i += 128) {
            int r = i >> 4, c = (i & 15) << 2;
            cp16(&Kb[buf * 64 * FST + r * FST + c],
                 &qkv[kbase + (size_t)r * N3 + c]);
            cp16(&Vb[buf * 64 * VST + r * VST + c],
                 &qkv[kbase + (size_t)r * N3 + C_ + c]);
        }
    };

    kv_load(0, 0);
    CP_COMMIT();

    for (int i = tid; i < 1024; i += 128) {
        int r = i >> 4, c = (i & 15) << 2;
        float4 t4 = *(const float4*)&qkv[qbase + (size_t)r * N3 + c];
        t4.x *= scale; t4.y *= scale; t4.z *= scale; t4.w *= scale;
        *(float4*)&QP[r * FST + c] = t4;
    }
    __syncthreads();

    unsigned aq[8][4];
    float* Pw = QP + w * 16 * FST;
#pragma unroll
    for (int kt = 0; kt < 8; kt++) {
        aq[kt][0] = __float_as_uint(Pw[g * FST + kt * 8 + qd]);
        aq[kt][1] = __float_as_uint(Pw[(g + 8) * FST + kt * 8 + qd]);
        aq[kt][2] = __float_as_uint(Pw[g * FST + kt * 8 + qd + 4]);
        aq[kt][3] = __float_as_uint(Pw[(g + 8) * FST + kt * 8 + qd + 4]);
    }
    __syncwarp();

    float oacc[8][4];
#pragma unroll
    for (int nt = 0; nt < 8; nt++)
#pragma unroll
        for (int j = 0; j < 4; j++) oacc[nt][j] = 0.0f;
    float mA = -INFINITY, mB = -INFINITY, lA = 0.0f, lB = 0.0f;

    const int rA_loc = w * 16 + g;
    const int rB_loc = rA_loc + 8;

    for (int n0 = 0; n0 <= q0; n0 += 64) {
        const int buf = (n0 >> 6) & 1;
        CP_WAIT(0);
        __syncthreads();
        if (n0 + 64 <= q0) {
            kv_load(buf ^ 1, n0 + 64);
            CP_COMMIT();
        }

        const float* Ks = &Kb[buf * 64 * FST];
        const float* Vs = &Vb[buf * 64 * VST];

        float s[8][4];
#pragma unroll
        for (int nt = 0; nt < 8; nt++)
#pragma unroll
            for (int j = 0; j < 4; j++) s[nt][j] = 0.0f;

#pragma unroll
        for (int kt = 0; kt < 8; kt++) {
#pragma unroll
            for (int nt = 0; nt < 8; nt++) {
                unsigned bb[2];
                bb[0] = __float_as_uint(Ks[(nt * 8 + g) * FST + kt * 8 + qd]);
                bb[1] = __float_as_uint(Ks[(nt * 8 + g) * FST + kt * 8 + qd + 4]);
                mma8(s[nt], aq[kt], bb);
            }
        }

        if (n0 == q0) {
#pragma unroll
            for (int nt = 0; nt < 8; nt++) {
                int c0 = nt * 8 + 2 * qd;
                if (c0     > rA_loc) s[nt][0] = -INFINITY;
                if (c0 + 1 > rA_loc) s[nt][1] = -INFINITY;
                if (c0     > rB_loc) s[nt][2] = -INFINITY;
                if (c0 + 1 > rB_loc) s[nt][3] = -INFINITY;
            }
        }

        float mxA = -INFINITY, mxB = -INFINITY;
#pragma unroll
        for (int nt = 0; nt < 8; nt++) {
            mxA = fmaxf(mxA, fmaxf(s[nt][0], s[nt][1]));
            mxB = fmaxf(mxB, fmaxf(s[nt][2], s[nt][3]));
        }
        mxA = fmaxf(mxA, __shfl_xor_sync(0xffffffffu, mxA, 1));
        mxA = fmaxf(mxA, __shfl_xor_sync(0xffffffffu, mxA, 2));
        mxB = fmaxf(mxB, __shfl_xor_sync(0xffffffffu, mxB, 1));
        mxB = fmaxf(mxB, __shfl_xor_sync(0xffffffffu, mxB, 2));

        float nmA = fmaxf(mA, mxA);
        float nmB = fmaxf(mB, mxB);
        float alA = __expf(mA - nmA);
        float alB = __expf(mB - nmB);
        mA = nmA; mB = nmB;

        float sumA = 0.0f, sumB = 0.0f;
#pragma unroll
        for (int nt = 0; nt < 8; nt++) {
            float p0 = __expf(s[nt][0] - nmA);
            float p1 = __expf(s[nt][1] - nmA);
            float p2 = __expf(s[nt][2] - nmB);
            float p3 = __expf(s[nt][3] - nmB);
            s[nt][0] = p0; s[nt][1] = p1; s[nt][2] = p2; s[nt][3] = p3;
            sumA += p0 + p1;
            sumB += p2 + p3;
        }
        sumA += __shfl_xor_sync(0xffffffffu, sumA, 1);
        sumA += __shfl_xor_sync(0xffffffffu, sumA, 2);
        sumB += __shfl_xor_sync(0xffffffffu, sumB, 1);
        sumB += __shfl_xor_sync(0xffffffffu, sumB, 2);
        lA = lA * alA + sumA;
        lB = lB * alB + sumB;

#pragma unroll
        for (int nt = 0; nt < 8; nt++) {
            oacc[nt][0] *= alA; oacc[nt][1] *= alA;
            oacc[nt][2] *= alB; oacc[nt][3] *= alB;
        }

#pragma unroll
        for (int nt = 0; nt < 8; nt++) {
            *(float2*)&Pw[g * FST + nt * 8 + 2 * qd] =
                make_float2(tf32r(s[nt][0]), tf32r(s[nt][1]));
            *(float2*)&Pw[(g + 8) * FST + nt * 8 + 2 * qd] =
                make_float2(tf32r(s[nt][2]), tf32r(s[nt][3]));
        }
        __syncwarp();

#pragma unroll
        for (int kt = 0; kt < 8; kt++) {
            unsigned ap[4];
            ap[0] = __float_as_uint(Pw[g * FST + kt * 8 + qd]);
            ap[1] = __float_as_uint(Pw[(g + 8) * FST + kt * 8 + qd]);
            ap[2] = __float_as_uint(Pw[g * FST + kt * 8 + qd + 4]);
            ap[3] = __float_as_uint(Pw[(g + 8) * FST + kt * 8 + qd + 4]);
#pragma unroll
            for (int nt = 0; nt < 8; nt++) {
                unsigned bb[2];
                bb[0] = __float_as_uint(Vs[(kt * 8 + qd) * VST + nt * 8 + g]);
                bb[1] = __float_as_uint(Vs[(kt * 8 + qd + 4) * VST + nt * 8 + g]);
                mma8(oacc[nt], ap, bb);
            }
        }
    }

    const float rA = 1.0f / lA;
    const float rB = 1.0f / lB;
#pragma unroll
    for (int nt = 0; nt < 8; nt++) {
        int c0 = nt * 8 + 2 * qd;
        *(float2*)&o[orow + (size_t)rA_loc * C_ + c0] =
            make_float2(tf32r(oacc[nt][0] * rA), tf32r(oacc[nt][1] * rA));
        *(float2*)&o[orow + (size_t)rB_loc * C_ + c0] =
            make_float2(tf32r(oacc[nt][2] * rB), tf32r(oacc[nt][3] * rB));
    }
}

// ---------------------------------------------------------------------------
extern "C" void kernel_launch(void* const* d_in, const int* in_sizes, int n_in,
                              void* d_out, int out_size)
{
    (void)in_sizes; (void)n_in; (void)out_size;
    const float* x  = (const float*)d_in[0];
    const float* Wq = (const float*)d_in[1];
    const float* Wk = (const float*)d_in[2];
    const float* Wv = (const float*)d_in[3];
    const float* Wo = (const float*)d_in[4];
    float* out = (float*)d_out;

    float *qkv, *ob, *xc, *wc;
    float2* tab;
    cudaGetSymbolAddress((void**)&qkv, g_qkv);
    cudaGetSymbolAddress((void**)&ob,  g_o);
    cudaGetSymbolAddress((void**)&xc,  g_xc);
    cudaGetSymbolAddress((void**)&wc,  g_wc);
    cudaGetSymbolAddress((void**)&tab, g_rope_tab);

    float* wqkv = wc;                          // [3C][C], contiguous
    float* woc  = wc + 3 * (size_t)C_ * C_;

    const int xn4 = M_ * C_ / 4, wn4 = C_ * C_ / 4;
    round_kernel<<<(xn4 + 255) / 256, 256>>>(x,  xc, xn4);
    round_kernel<<<(wn4 + 255) / 256, 256>>>(Wq, wqkv,                       wn4);
    round_kernel<<<(wn4 + 255) / 256, 256>>>(Wk, wqkv + (size_t)C_ * C_,     wn4);
    round_kernel<<<(wn4 + 255) / 256, 256>>>(Wv, wqkv + 2 * (size_t)C_ * C_, wn4);
    round_kernel<<<(wn4 + 255) / 256, 256>>>(Wo, woc,                        wn4);
    rope_table_kernel<<<(T_ * 32 + 255) / 256, 256>>>(tab);

    const int gsmem = 6 * 128 * GST * (int)sizeof(float);   // 110,592 B
    cudaFuncSetAttribute(gemm_tn,
                         cudaFuncAttributeMaxDynamicSharedMemorySize, gsmem);

    // fused QKV projection: Y[M, 3C] = x @ [Wq;Wk;Wv]^T
    gemm_tn<<<dim3(N3 / 128, M_ / 128), 128, gsmem>>>(xc, wqkv, qkv,
                                                      M_, N3, C_);

    const int pairs = M_ * (C_ / 2);
    rope_apply_kernel<<<(pairs + 255) / 256, 256>>>(qkv, tab);

    const int fsmem = (64 * FST + 128 * FST + 128 * VST) * (int)sizeof(float);
    cudaFuncSetAttribute(flash_kernel,
                         cudaFuncAttributeMaxDynamicSharedMemorySize, fsmem);
    flash_kernel<<<dim3(T_ / 64, B_ * H_), 128, fsmem>>>(qkv, ob);

    gemm_tn<<<dim3(C_ / 128, M_ / 128), 128, gsmem>>>(ob, woc, out,
                                                      M_, C_, C_);
}